// round 16
// baseline (speedup 1.0000x reference)
#include <cuda_runtime.h>
#include <cuda_fp16.h>
#include <math.h>

#define TINF 3.0e38f
#define TT   1024
#define BB   32
#define DDIM 64
#define RS   1024        // halves per diag row
#define DROWS 2048       // rows 0..2046 used; predicate caps loads at 2047
#define INF2 0x7C007C00u // half2 (+inf, +inf)

// Diag-major SQUARED cost [b][d][j] in fp16 (DP runs on d^2; sqrt on the final
// per-batch scalar). Valid cells written by cost role; 2 boundary cells per row
// pre-set +inf by the pre-kernel. Deep-invalid cells unreachable (NaN-safe min/max).
__device__ __half g_cost[(size_t)BB * DROWS * RS];
__device__ float g_n2[2 * BB * TT];
__device__ float g_bdist[BB];
__device__ int   g_cnt[BB * 15];     // finished tiles per (batch, tile-antidiag)
__device__ unsigned g_done;          // dp completion ticket

// Tile visit order: (it,jt) sorted by g=it+jt (it*8+jt encoded).
__device__ const unsigned char g_order[64] = {
    0,
    1, 8,
    2, 9, 16,
    3, 10, 17, 24,
    4, 11, 18, 25, 32,
    5, 12, 19, 26, 33, 40,
    6, 13, 20, 27, 34, 41, 48,
    7, 14, 21, 28, 35, 42, 49, 56,
    15, 22, 29, 36, 43, 50, 57,
    23, 30, 37, 44, 51, 58,
    31, 38, 45, 52, 59,
    39, 46, 53, 60,
    47, 54, 61,
    55, 62,
    63
};

// ---------------------------------------------------------------------------
// Pre-kernel: blocks [0,8192) = row norms (byte-identical math to the old
// norms_kernel); blocks [8192,8448) = boundary +inf init + counter reset.
// ---------------------------------------------------------------------------
__global__ void pre_kernel(const float* __restrict__ pred,
                           const float* __restrict__ targ) {
    if (blockIdx.x < 8192) {
        int gw   = (blockIdx.x * blockDim.x + threadIdx.x) >> 5;
        int lane = threadIdx.x & 31;
        if (gw >= 2 * BB * TT) return;
        const float* src = (gw < BB * TT) ? (pred + (size_t)gw * DDIM)
                                          : (targ + (size_t)(gw - BB * TT) * DDIM);
        float x0 = src[lane], x1 = src[lane + 32];
        float s = x0 * x0 + x1 * x1;
        #pragma unroll
        for (int o = 16; o > 0; o >>= 1) s += __shfl_down_sync(0xffffffffu, s, o);
        if (lane == 0) g_n2[gw] = s;
    } else {
        int i = (blockIdx.x - 8192) * blockDim.x + threadIdx.x;
        if (i == 0) g_done = 0;
        if (i < BB * 15) g_cnt[i] = 0;
        int b = i >> 11, d = i & 2047;
        if (b >= BB) return;
        unsigned short* row = (unsigned short*)(g_cost + ((size_t)b * DROWS + d) * RS);
        if (d <= 1022)                   row[d + 1]    = 0x7C00;
        else if (d >= 1024 && d <= 2046) row[d - 1024] = 0x7C00;
    }
}

// ---------------------------------------------------------------------------
// TF32 mma helpers.
// ---------------------------------------------------------------------------
__device__ __forceinline__ unsigned f2tf(float x) {
    unsigned u;
    asm("cvt.rna.tf32.f32 %0, %1;" : "=r"(u) : "f"(x));
    return u;
}
__device__ __forceinline__ void mma_tf32(float c[4], const unsigned a[4],
                                         const unsigned b[2]) {
    asm volatile(
        "mma.sync.aligned.m16n8k8.row.col.f32.tf32.tf32.f32 "
        "{%0,%1,%2,%3}, {%4,%5,%6,%7}, {%8,%9}, {%0,%1,%2,%3};"
        : "+f"(c[0]), "+f"(c[1]), "+f"(c[2]), "+f"(c[3])
        : "r"(a[0]), "r"(a[1]), "r"(a[2]), "r"(a[3]), "r"(b[0]), "r"(b[1]));
}

#define SKP 36
#define RING    10
#define SROWH   1032                   // halves per staged row (4 guard + 1024 + 4 pad)
#define SSTAGEH (4 * SROWH)
#define DPDYN   (RING * SSTAGEH * 2)   // 82,560 B dynamic -> 2 CTAs/SM

__device__ __forceinline__ void cpa8(unsigned dst, const __half* src) {
    asm volatile("cp.async.ca.shared.global [%0], [%1], 8;"
                 :: "r"(dst), "l"(src));
}

// half2 min/max on raw uints (NaN-discarding, exact selection).
__device__ __forceinline__ unsigned hmin2u(unsigned a, unsigned b) {
    __half2 r = __hmin2(*(__half2*)&a, *(__half2*)&b);
    return *(unsigned*)&r;
}
__device__ __forceinline__ unsigned hmax2u(unsigned a, unsigned b) {
    __half2 r = __hmax2(*(__half2*)&a, *(__half2*)&b);
    return *(unsigned*)&r;
}
// Misaligned pair (a.hi, b.lo) in one PRMT.
#define SH(a, b) __byte_perm((a), (b), 0x5432)

// ---------------------------------------------------------------------------
// Cost role: TF32 tiles -> fp16 d^2, diag-major (unchanged from R13/R14).
// ---------------------------------------------------------------------------
__device__ void cost_role(char* dyn, const float* __restrict__ pred,
                          const float* __restrict__ targ, int cbid) {
    int b  = cbid & 31;
    int code = g_order[cbid >> 5];
    int it = code >> 3, jt = code & 7;
    int i0 = it * 128, j0 = jt * 128;
    const float* A  = pred + (size_t)b * TT * DDIM;
    const float* Bm = targ + (size_t)b * TT * DDIM;

    float* smbuf = (float*)dyn;
    float* sA = smbuf;
    float* sB = smbuf + 128 * SKP;
    float* Cs = smbuf;

    int tid  = threadIdx.x;
    int lane = tid & 31, w = tid >> 5;
    int g    = lane >> 2, tig = lane & 3;
    int wm   = (w & 3) * 32, wn = (w >> 2) * 64;

    float c[2][8][4];
    #pragma unroll
    for (int mt = 0; mt < 2; ++mt)
        #pragma unroll
        for (int nt = 0; nt < 8; ++nt)
            #pragma unroll
            for (int e = 0; e < 4; ++e) c[mt][nt][e] = 0.f;

    int lr = tid >> 1;
    int lk = (tid & 1) * 16;
    const float* ga = A  + (size_t)(i0 + lr) * DDIM + lk;
    const float* gb = Bm + (size_t)(j0 + lr) * DDIM + lk;

    #pragma unroll 1
    for (int kc = 0; kc < 64; kc += 32) {
        #pragma unroll
        for (int c4 = 0; c4 < 4; ++c4) {
            float4 va = *(const float4*)(ga + kc + c4 * 4);
            float4 vb = *(const float4*)(gb + kc + c4 * 4);
            int o = lr * SKP + lk + c4 * 4;
            sA[o + 0] = __uint_as_float(f2tf(va.x));
            sA[o + 1] = __uint_as_float(f2tf(va.y));
            sA[o + 2] = __uint_as_float(f2tf(va.z));
            sA[o + 3] = __uint_as_float(f2tf(va.w));
            sB[o + 0] = __uint_as_float(f2tf(vb.x));
            sB[o + 1] = __uint_as_float(f2tf(vb.y));
            sB[o + 2] = __uint_as_float(f2tf(vb.z));
            sB[o + 3] = __uint_as_float(f2tf(vb.w));
        }
        __syncthreads();

        #pragma unroll
        for (int ks = 0; ks < 32; ks += 8) {
            unsigned af[2][4], bf[8][2];
            #pragma unroll
            for (int mt = 0; mt < 2; ++mt) {
                int mr = wm + mt * 16;
                af[mt][0] = __float_as_uint(sA[(mr + g)     * SKP + ks + tig]);
                af[mt][1] = __float_as_uint(sA[(mr + g + 8) * SKP + ks + tig]);
                af[mt][2] = __float_as_uint(sA[(mr + g)     * SKP + ks + tig + 4]);
                af[mt][3] = __float_as_uint(sA[(mr + g + 8) * SKP + ks + tig + 4]);
            }
            #pragma unroll
            for (int nt = 0; nt < 8; ++nt) {
                int nr = wn + nt * 8 + g;
                bf[nt][0] = __float_as_uint(sB[nr * SKP + ks + tig]);
                bf[nt][1] = __float_as_uint(sB[nr * SKP + ks + tig + 4]);
            }
            #pragma unroll
            for (int mt = 0; mt < 2; ++mt)
                #pragma unroll
                for (int nt = 0; nt < 8; ++nt)
                    mma_tf32(c[mt][nt], af[mt], bf[nt]);
        }
        __syncthreads();
    }

    float a2v[2][2], b2v[8][2];
    #pragma unroll
    for (int mt = 0; mt < 2; ++mt) {
        a2v[mt][0] = g_n2[b * TT + i0 + wm + mt * 16 + g];
        a2v[mt][1] = g_n2[b * TT + i0 + wm + mt * 16 + g + 8];
    }
    #pragma unroll
    for (int nt = 0; nt < 8; ++nt) {
        b2v[nt][0] = g_n2[BB * TT + b * TT + j0 + wn + nt * 8 + 2 * tig];
        b2v[nt][1] = g_n2[BB * TT + b * TT + j0 + wn + nt * 8 + 2 * tig + 1];
    }

    __half* out = g_cost + (size_t)b * DROWS * RS;

    #pragma unroll 1
    for (int qq = 0; qq < 4; ++qq) {
        int qi = qq >> 1, qj = qq & 1;
        __syncthreads();
        if ((w >> 2) == qj && ((w & 3) >> 1) == qi) {
            int mloc0 = ((w & 3) & 1) * 32;
            #pragma unroll
            for (int mt = 0; mt < 2; ++mt) {
                int ml = mloc0 + mt * 16 + g;
                #pragma unroll
                for (int nt = 0; nt < 8; ++nt) {
                    int nl = nt * 8 + 2 * tig;
                    float s0 = a2v[mt][0] + b2v[nt][0] - 2.0f * c[mt][nt][0];
                    float s1 = a2v[mt][0] + b2v[nt][1] - 2.0f * c[mt][nt][1];
                    float s2 = a2v[mt][1] + b2v[nt][0] - 2.0f * c[mt][nt][2];
                    float s3 = a2v[mt][1] + b2v[nt][1] - 2.0f * c[mt][nt][3];
                    Cs[ml * 66 + nl]           = fmaxf(s0, 1e-12f);
                    Cs[ml * 66 + nl + 1]       = fmaxf(s1, 1e-12f);
                    Cs[(ml + 8) * 66 + nl]     = fmaxf(s2, 1e-12f);
                    Cs[(ml + 8) * 66 + nl + 1] = fmaxf(s3, 1e-12f);
                }
            }
        }
        __syncthreads();

        int i0q = i0 + qi * 64, j0q = j0 + qj * 64;
        int D0 = i0q + j0q;
        for (int dd = w; dd < 127; dd += 8) {
            int jl = max(0, dd - 63);
            int jh = min(dd, 63);
            int L = jh - jl + 1;
            size_t gbase = (size_t)(D0 + dd) * RS + (size_t)(j0q + jl);
            for (int l = lane; l < L; l += 32) {
                int j = jl + l;
                out[gbase + l] = __float2half(Cs[(dd - j) * 66 + j]);
            }
        }
    }

    __threadfence();
    __syncthreads();
    if (tid == 0) atomicAdd(&g_cnt[b * 15 + (it + jt)], 1);
}

// ---------------------------------------------------------------------------
// DP role: R14 semantics bit-exact, with dead computations eliminated.
// Level l (diag d0+l) is valid only for ext >= l+1, so only 4+3+3+2 pair
// computations are live (verified lane-by-lane: dropped values fed only
// dropped lanes). Availability poll hoisted to a trigger-superstep compare
// (group g first needed at s = 32g-9). Last dp CTA performs the final
// sqrt-mean reduction via an atomic ticket (no separate reduce kernel).
// ---------------------------------------------------------------------------
__device__ void dp_role(char* dyn, float* outp) {
    __half* dsmh = (__half*)dyn;
    int b    = blockIdx.x;
    int t    = threadIdx.x;
    int w    = t >> 5;
    int lane = t & 31;
    int j0   = t << 2;
    const __half* SC = g_cost + (size_t)b * DROWS * RS;

    __shared__ uint4 swpq[2][8];   // per-warp boundary: (p01,p23,q01,q23)
    if (t < 16) ((uint4*)swpq)[t] = make_uint4(INF2, INF2, INF2, INF2);
    for (int i = t; i < RING * 4; i += 256) {
        unsigned* gr = (unsigned*)(dsmh + i * SROWH);
        gr[0] = INF2; gr[1] = INF2;
    }
    __syncthreads();

    unsigned smu = (unsigned)__cvta_generic_to_shared(dsmh) + (unsigned)(4 + j0) * 2;

    #define DP_ON(d) ((unsigned)((d) - j0 + 1) <= 1028u)

    // Availability: rows <= 128*G+127 ready once all tile-groups <= G done.
    int done_groups = 0;
    const volatile int* cnt = (const volatile int*)(g_cnt + b * 15);
    while (done_groups <= 0) {
        if (cnt[0] >= 1) done_groups = 1;
    }
    __threadfence();

    for (int s = 0; s < RING - 1; ++s) {
        const __half* src = SC + (size_t)(4 * s) * RS + j0;
        unsigned d = smu + s * (SSTAGEH * 2);
        #pragma unroll
        for (int k = 0; k < 4; ++k)
            if (DP_ON(4 * s + k)) cpa8(d + k * (SROWH * 2), src + (size_t)k * RS);
        asm volatile("cp.async.commit_group;");
    }

    unsigned p01 = INF2, p23 = INF2;   // own cols (j0..j0+3), diag d0-1
    unsigned q01 = INF2, q23 = INF2;   // diag d0-2
    float res  = 0.f;
    int stage  = 0;
    int s_trig = 32 * 1 - 9;           // superstep at which group done_groups is needed

    #pragma unroll 1
    for (int s = 0; s < 512; ++s) {
        asm volatile("cp.async.wait_group 8;");
        __syncthreads();

        const __half* bp = dsmh + stage * SSTAGEH;
        // Row 0..2: halo pair + own pair; row 3: own only (halo never consumed).
        uint2 h0 = *(const uint2*)(bp + 0 * SROWH + j0);
        uint2 o0 = *(const uint2*)(bp + 0 * SROWH + j0 + 4);
        uint2 h1 = *(const uint2*)(bp + 1 * SROWH + j0);
        uint2 o1 = *(const uint2*)(bp + 1 * SROWH + j0 + 4);
        uint2 h2 = *(const uint2*)(bp + 2 * SROWH + j0);
        uint2 o2 = *(const uint2*)(bp + 2 * SROWH + j0 + 4);
        uint2 o3 = *(const uint2*)(bp + 3 * SROWH + j0 + 4);

        // Halo: left neighbor's own pairs (their registers hold last superstep).
        unsigned hp01 = __shfl_up_sync(0xffffffffu, p01, 1);
        unsigned hp23 = __shfl_up_sync(0xffffffffu, p23, 1);
        unsigned hq01 = __shfl_up_sync(0xffffffffu, q01, 1);
        unsigned hq23 = __shfl_up_sync(0xffffffffu, q23, 1);
        if (lane == 0) {
            if (w == 0) {
                hp01 = hp23 = hq01 = INF2;
                hq23 = (s == 0) ? 0xFC007C00u : INF2;   // seed ca[-1][-1]
            } else {
                uint4 m = swpq[s & 1][w - 1];
                hp01 = m.x; hp23 = m.y; hq01 = m.z; hq23 = m.w;
            }
        }

        unsigned P[4]  = {hp01, hp23, p01, p23};
        unsigned Ps[4] = {SH(INF2, P[0]), SH(P[0], P[1]), SH(P[1], P[2]), SH(P[2], P[3])};
        unsigned Qs[4] = {SH(INF2, hq01), SH(hq01, hq23), SH(hq23, q01), SH(q01, q23)};

        // Level 0 (diag d0): all 4 pairs (ext1 onward needed downstream).
        unsigned L00 = hmax2u(h0.x, hmin2u(hmin2u(P[0], Ps[0]), Qs[0]));
        unsigned L01 = hmax2u(h0.y, hmin2u(hmin2u(P[1], Ps[1]), Qs[1]));
        unsigned L02 = hmax2u(o0.x, hmin2u(hmin2u(P[2], Ps[2]), Qs[2]));
        unsigned L03 = hmax2u(o0.y, hmin2u(hmin2u(P[3], Ps[3]), Qs[3]));
        unsigned L0s1 = SH(L00, L01), L0s2 = SH(L01, L02), L0s3 = SH(L02, L03);

        // Level 1 (diag d0+1): pairs 1..3 (pair 0 fed only dropped lanes).
        unsigned L11 = hmax2u(h1.y, hmin2u(hmin2u(L01, L0s1), Ps[1]));
        unsigned L12 = hmax2u(o1.x, hmin2u(hmin2u(L02, L0s2), Ps[2]));
        unsigned L13 = hmax2u(o1.y, hmin2u(hmin2u(L03, L0s3), Ps[3]));
        unsigned L1s1 = SH(INF2, L11);   // low lane feeds a garbage cell only
        unsigned L1s2 = SH(L11, L12), L1s3 = SH(L12, L13);

        // Level 2 (diag d0+2): pairs 1..3.
        unsigned L21 = hmax2u(h2.y, hmin2u(hmin2u(L11, L1s1), L0s1));
        unsigned L22 = hmax2u(o2.x, hmin2u(hmin2u(L12, L1s2), L0s2));
        unsigned L23 = hmax2u(o2.y, hmin2u(hmin2u(L13, L1s3), L0s3));
        unsigned L2s2 = SH(L21, L22), L2s3 = SH(L22, L23);

        // Level 3 (diag d0+3): pairs 2..3 (own cols only).
        unsigned L32 = hmax2u(o3.x, hmin2u(hmin2u(L22, L2s2), L1s2));
        unsigned L33 = hmax2u(o3.y, hmin2u(hmin2u(L23, L2s3), L1s3));

        if (lane == 31)
            swpq[(s + 1) & 1][w] = make_uint4(L32, L33, L22, L23);
        if (s == 511) res = __high2float(*(__half2*)&L23);   // diag 2046, col 1023

        p01 = L32; p23 = L33; q01 = L22; q23 = L23;

        // Availability trigger: group done_groups first needed at s = 32g-9.
        if (s == s_trig) {
            int tn = (done_groups <= 7) ? done_groups + 1 : 15 - done_groups;
            while (cnt[done_groups] < tn) { }
            __threadfence();
            ++done_groups;
            s_trig = (done_groups < 15) ? 32 * done_groups - 9 : 0x7FFFFFFF;
        }

        // Issue stage s+9 into the buffer consumed at body s-1 (race-free).
        {
            int st2 = stage + (RING - 1); if (st2 >= RING) st2 -= RING;
            int dbase = 4 * (s + RING - 1);
            const __half* src = SC + (size_t)dbase * RS + j0;
            unsigned d = smu + st2 * (SSTAGEH * 2);
            #pragma unroll
            for (int k = 0; k < 4; ++k)
                if (DP_ON(dbase + k)) cpa8(d + k * (SROWH * 2), src + (size_t)k * RS);
            asm volatile("cp.async.commit_group;");
        }
        if (++stage == RING) stage = 0;
    }

    if (t == 255) {
        g_bdist[b] = res;
        __threadfence();
        unsigned tk = atomicAdd(&g_done, 1u);
        if (tk == BB - 1) {                  // last dp CTA: final sqrt-mean
            __threadfence();
            float sum = 0.f;
            #pragma unroll 1
            for (int i = 0; i < BB; ++i)
                sum += sqrtf(((volatile float*)g_bdist)[i]);
            outp[0] = sum * (1.0f / BB);
        }
    }
    #undef DP_ON
}

// ---------------------------------------------------------------------------
// Fused kernel: bids 0..31 = DP consumers (wave-1 resident; never block
// producers => no deadlock), bids 32..2079 = cost producers.
// ---------------------------------------------------------------------------
__global__ void __launch_bounds__(256, 2) fused_kernel(const float* __restrict__ pred,
                                                       const float* __restrict__ targ,
                                                       float* outp) {
    extern __shared__ __align__(16) char dyn[];
    if (blockIdx.x < 32) dp_role(dyn, outp);
    else                 cost_role(dyn, pred, targ, blockIdx.x - 32);
}

// ---------------------------------------------------------------------------
extern "C" void kernel_launch(void* const* d_in, const int* in_sizes, int n_in,
                              void* d_out, int out_size) {
    const float* pred = (const float*)d_in[0];
    const float* targ = (const float*)d_in[1];
    (void)in_sizes; (void)n_in; (void)out_size;

    cudaFuncSetAttribute(fused_kernel,
                         cudaFuncAttributeMaxDynamicSharedMemorySize, DPDYN);

    pre_kernel<<<8448, 256>>>(pred, targ);
    fused_kernel<<<2080, 256, DPDYN>>>(pred, targ, (float*)d_out);
}

// round 17
// speedup vs baseline: 1.0003x; 1.0003x over previous
#include <cuda_runtime.h>
#include <cuda_fp16.h>
#include <math.h>

#define TINF 3.0e38f
#define TT   1024
#define BB   32
#define DDIM 64
#define RS   1024        // halves per diag row
#define DROWS 2056       // rows 0..2046 used; widened predicate caps loads at 2055
#define INF2 0x7C007C00u // half2 (+inf, +inf)

// Diag-major SQUARED cost [b][d][j] in fp16 (DP runs on d^2; sqrt on the final
// per-batch scalar). Valid cells written by cost role; 2 boundary cells per row
// pre-set +inf by the pre-kernel. Deep-invalid cells (and rows >= 2047) stay
// garbage: provably blocked by +inf boundary cells (NaN-discarding min/max).
__device__ __half g_cost[(size_t)BB * DROWS * RS];
__device__ float g_n2[2 * BB * TT];
__device__ float g_bdist[BB];
__device__ int   g_cnt[BB * 15];     // finished tiles per (batch, tile-antidiag)
__device__ unsigned g_done;          // dp completion ticket

// Tile visit order: (it,jt) sorted by g=it+jt (it*8+jt encoded).
__device__ const unsigned char g_order[64] = {
    0,
    1, 8,
    2, 9, 16,
    3, 10, 17, 24,
    4, 11, 18, 25, 32,
    5, 12, 19, 26, 33, 40,
    6, 13, 20, 27, 34, 41, 48,
    7, 14, 21, 28, 35, 42, 49, 56,
    15, 22, 29, 36, 43, 50, 57,
    23, 30, 37, 44, 51, 58,
    31, 38, 45, 52, 59,
    39, 46, 53, 60,
    47, 54, 61,
    55, 62,
    63
};

// ---------------------------------------------------------------------------
// Pre-kernel: blocks [0,8192) = row norms; [8192,8448) = boundary init + counters.
// ---------------------------------------------------------------------------
__global__ void pre_kernel(const float* __restrict__ pred,
                           const float* __restrict__ targ) {
    if (blockIdx.x < 8192) {
        int gw   = (blockIdx.x * blockDim.x + threadIdx.x) >> 5;
        int lane = threadIdx.x & 31;
        if (gw >= 2 * BB * TT) return;
        const float* src = (gw < BB * TT) ? (pred + (size_t)gw * DDIM)
                                          : (targ + (size_t)(gw - BB * TT) * DDIM);
        float x0 = src[lane], x1 = src[lane + 32];
        float s = x0 * x0 + x1 * x1;
        #pragma unroll
        for (int o = 16; o > 0; o >>= 1) s += __shfl_down_sync(0xffffffffu, s, o);
        if (lane == 0) g_n2[gw] = s;
    } else {
        int i = (blockIdx.x - 8192) * blockDim.x + threadIdx.x;
        if (i == 0) g_done = 0;
        if (i < BB * 15) g_cnt[i] = 0;
        int b = i >> 11, d = i & 2047;
        if (b >= BB) return;
        unsigned short* row = (unsigned short*)(g_cost + ((size_t)b * DROWS + d) * RS);
        if (d <= 1022)                   row[d + 1]    = 0x7C00;
        else if (d >= 1024 && d <= 2046) row[d - 1024] = 0x7C00;
    }
}

// ---------------------------------------------------------------------------
// TF32 mma helpers.
// ---------------------------------------------------------------------------
__device__ __forceinline__ unsigned f2tf(float x) {
    unsigned u;
    asm("cvt.rna.tf32.f32 %0, %1;" : "=r"(u) : "f"(x));
    return u;
}
__device__ __forceinline__ void mma_tf32(float c[4], const unsigned a[4],
                                         const unsigned b[2]) {
    asm volatile(
        "mma.sync.aligned.m16n8k8.row.col.f32.tf32.tf32.f32 "
        "{%0,%1,%2,%3}, {%4,%5,%6,%7}, {%8,%9}, {%0,%1,%2,%3};"
        : "+f"(c[0]), "+f"(c[1]), "+f"(c[2]), "+f"(c[3])
        : "r"(a[0]), "r"(a[1]), "r"(a[2]), "r"(a[3]), "r"(b[0]), "r"(b[1]));
}

#define SKP 36
#define RING    6
#define SROWH   1036                   // halves per staged row (8 guard + 1024 + 4 pad)
#define SSTAGEH (8 * SROWH)            // 8 rows per stage
#define DPDYN   (RING * SSTAGEH * 2)   // 99,456 B dynamic -> 2 CTAs/SM

__device__ __forceinline__ void cpa8(unsigned dst, const __half* src) {
    asm volatile("cp.async.ca.shared.global [%0], [%1], 8;"
                 :: "r"(dst), "l"(src));
}

// half2 min/max on raw uints (NaN-discarding, exact selection).
__device__ __forceinline__ unsigned hmin2u(unsigned a, unsigned b) {
    __half2 r = __hmin2(*(__half2*)&a, *(__half2*)&b);
    return *(unsigned*)&r;
}
__device__ __forceinline__ unsigned hmax2u(unsigned a, unsigned b) {
    __half2 r = __hmax2(*(__half2*)&a, *(__half2*)&b);
    return *(unsigned*)&r;
}
// Misaligned pair (a.hi, b.lo) in one PRMT.
#define SH(a, b) __byte_perm((a), (b), 0x5432)

// ---------------------------------------------------------------------------
// Cost role: TF32 tiles -> fp16 d^2, diag-major (unchanged from R13/R14/R16).
// ---------------------------------------------------------------------------
__device__ void cost_role(char* dyn, const float* __restrict__ pred,
                          const float* __restrict__ targ, int cbid) {
    int b  = cbid & 31;
    int code = g_order[cbid >> 5];
    int it = code >> 3, jt = code & 7;
    int i0 = it * 128, j0 = jt * 128;
    const float* A  = pred + (size_t)b * TT * DDIM;
    const float* Bm = targ + (size_t)b * TT * DDIM;

    float* smbuf = (float*)dyn;
    float* sA = smbuf;
    float* sB = smbuf + 128 * SKP;
    float* Cs = smbuf;

    int tid  = threadIdx.x;
    int lane = tid & 31, w = tid >> 5;
    int g    = lane >> 2, tig = lane & 3;
    int wm   = (w & 3) * 32, wn = (w >> 2) * 64;

    float c[2][8][4];
    #pragma unroll
    for (int mt = 0; mt < 2; ++mt)
        #pragma unroll
        for (int nt = 0; nt < 8; ++nt)
            #pragma unroll
            for (int e = 0; e < 4; ++e) c[mt][nt][e] = 0.f;

    int lr = tid >> 1;
    int lk = (tid & 1) * 16;
    const float* ga = A  + (size_t)(i0 + lr) * DDIM + lk;
    const float* gb = Bm + (size_t)(j0 + lr) * DDIM + lk;

    #pragma unroll 1
    for (int kc = 0; kc < 64; kc += 32) {
        #pragma unroll
        for (int c4 = 0; c4 < 4; ++c4) {
            float4 va = *(const float4*)(ga + kc + c4 * 4);
            float4 vb = *(const float4*)(gb + kc + c4 * 4);
            int o = lr * SKP + lk + c4 * 4;
            sA[o + 0] = __uint_as_float(f2tf(va.x));
            sA[o + 1] = __uint_as_float(f2tf(va.y));
            sA[o + 2] = __uint_as_float(f2tf(va.z));
            sA[o + 3] = __uint_as_float(f2tf(va.w));
            sB[o + 0] = __uint_as_float(f2tf(vb.x));
            sB[o + 1] = __uint_as_float(f2tf(vb.y));
            sB[o + 2] = __uint_as_float(f2tf(vb.z));
            sB[o + 3] = __uint_as_float(f2tf(vb.w));
        }
        __syncthreads();

        #pragma unroll
        for (int ks = 0; ks < 32; ks += 8) {
            unsigned af[2][4], bf[8][2];
            #pragma unroll
            for (int mt = 0; mt < 2; ++mt) {
                int mr = wm + mt * 16;
                af[mt][0] = __float_as_uint(sA[(mr + g)     * SKP + ks + tig]);
                af[mt][1] = __float_as_uint(sA[(mr + g + 8) * SKP + ks + tig]);
                af[mt][2] = __float_as_uint(sA[(mr + g)     * SKP + ks + tig + 4]);
                af[mt][3] = __float_as_uint(sA[(mr + g + 8) * SKP + ks + tig + 4]);
            }
            #pragma unroll
            for (int nt = 0; nt < 8; ++nt) {
                int nr = wn + nt * 8 + g;
                bf[nt][0] = __float_as_uint(sB[nr * SKP + ks + tig]);
                bf[nt][1] = __float_as_uint(sB[nr * SKP + ks + tig + 4]);
            }
            #pragma unroll
            for (int mt = 0; mt < 2; ++mt)
                #pragma unroll
                for (int nt = 0; nt < 8; ++nt)
                    mma_tf32(c[mt][nt], af[mt], bf[nt]);
        }
        __syncthreads();
    }

    float a2v[2][2], b2v[8][2];
    #pragma unroll
    for (int mt = 0; mt < 2; ++mt) {
        a2v[mt][0] = g_n2[b * TT + i0 + wm + mt * 16 + g];
        a2v[mt][1] = g_n2[b * TT + i0 + wm + mt * 16 + g + 8];
    }
    #pragma unroll
    for (int nt = 0; nt < 8; ++nt) {
        b2v[nt][0] = g_n2[BB * TT + b * TT + j0 + wn + nt * 8 + 2 * tig];
        b2v[nt][1] = g_n2[BB * TT + b * TT + j0 + wn + nt * 8 + 2 * tig + 1];
    }

    __half* out = g_cost + (size_t)b * DROWS * RS;

    #pragma unroll 1
    for (int qq = 0; qq < 4; ++qq) {
        int qi = qq >> 1, qj = qq & 1;
        __syncthreads();
        if ((w >> 2) == qj && ((w & 3) >> 1) == qi) {
            int mloc0 = ((w & 3) & 1) * 32;
            #pragma unroll
            for (int mt = 0; mt < 2; ++mt) {
                int ml = mloc0 + mt * 16 + g;
                #pragma unroll
                for (int nt = 0; nt < 8; ++nt) {
                    int nl = nt * 8 + 2 * tig;
                    float s0 = a2v[mt][0] + b2v[nt][0] - 2.0f * c[mt][nt][0];
                    float s1 = a2v[mt][0] + b2v[nt][1] - 2.0f * c[mt][nt][1];
                    float s2 = a2v[mt][1] + b2v[nt][0] - 2.0f * c[mt][nt][2];
                    float s3 = a2v[mt][1] + b2v[nt][1] - 2.0f * c[mt][nt][3];
                    Cs[ml * 66 + nl]           = fmaxf(s0, 1e-12f);
                    Cs[ml * 66 + nl + 1]       = fmaxf(s1, 1e-12f);
                    Cs[(ml + 8) * 66 + nl]     = fmaxf(s2, 1e-12f);
                    Cs[(ml + 8) * 66 + nl + 1] = fmaxf(s3, 1e-12f);
                }
            }
        }
        __syncthreads();

        int i0q = i0 + qi * 64, j0q = j0 + qj * 64;
        int D0 = i0q + j0q;
        for (int dd = w; dd < 127; dd += 8) {
            int jl = max(0, dd - 63);
            int jh = min(dd, 63);
            int L = jh - jl + 1;
            size_t gbase = (size_t)(D0 + dd) * RS + (size_t)(j0q + jl);
            for (int l = lane; l < L; l += 32) {
                int j = jl + l;
                out[gbase + l] = __float2half(Cs[(dd - j) * 66 + j]);
            }
        }
    }

    __threadfence();
    __syncthreads();
    if (tid == 0) atomicAdd(&g_cnt[b * 15 + (it + jt)], 1);
}

// ---------------------------------------------------------------------------
// DP role: EIGHT diagonals per superstep (256 barriers). Band predicate FIXED:
// a staged row serves threads t, t+1, t+2 (ext window 12), so thread t stages
// d in [j0-1, j0+1035] (<= 1036 in the unsigned form) — R15's 1028 leaked
// unstaged garbage into valid cells near the j=d-1023 boundary. With the fix,
// selection is bit-identical to the fp32 reference path. Availability spins
// hoisted to trigger supersteps (group g first needed at s = 16g-5). Last dp
// CTA does the final sqrt-mean via an atomic ticket.
// ---------------------------------------------------------------------------
__device__ void dp_role(char* dyn, float* outp) {
    __half* dsmh = (__half*)dyn;
    int b    = blockIdx.x;
    int t    = threadIdx.x;
    int w    = t >> 5;
    int lane = t & 31;
    int j0   = t << 2;
    const __half* SC = g_cost + (size_t)b * DROWS * RS;

    __shared__ uint4 swm[2][8][2];   // [buf][warp][lane-30]: (p01,p23,q01,q23)
    if (t < 32) ((uint4*)swm)[t] = make_uint4(INF2, INF2, INF2, INF2);
    for (int i = t; i < RING * 8; i += 256) {       // 8-half +inf guards per row
        unsigned* gr = (unsigned*)(dsmh + i * SROWH);
        gr[0] = INF2; gr[1] = INF2; gr[2] = INF2; gr[3] = INF2;
    }
    __syncthreads();

    unsigned smu = (unsigned)__cvta_generic_to_shared(dsmh) + (unsigned)(8 + j0) * 2;

    // FIXED band: stage row d iff d in [j0-1, j0+1035].
    #define DP_ON(d) ((unsigned)((d) - j0 + 1) <= 1036u)

    // Availability: rows <= 128*G+127 ready once all tile-groups <= G done.
    int done_groups = 0;
    const volatile int* cnt = (const volatile int*)(g_cnt + b * 15);
    while (done_groups <= 0) {
        if (cnt[0] >= 1) done_groups = 1;
    }
    __threadfence();

    // Prologue: stages 0..4 (rows 0..39, group 0 only).
    for (int st = 0; st < RING - 1; ++st) {
        #pragma unroll
        for (int k = 0; k < 8; ++k)
            if (DP_ON(8 * st + k))
                cpa8(smu + (st * 8 + k) * (SROWH * 2),
                     SC + (size_t)(8 * st + k) * RS + j0);
        asm volatile("cp.async.commit_group;");
    }

    unsigned p01 = INF2, p23 = INF2;   // own cols (j0..j0+3), diag d0-1
    unsigned q01 = INF2, q23 = INF2;   // diag d0-2
    float res  = 0.f;
    int stage  = 0;
    int s_trig = 16 * 1 - 5;           // superstep at which group done_groups is needed

    // 256 supersteps x 8 diagonals = 2048 (res latched at s=255, level 6 = diag 2046).
    #pragma unroll 1
    for (int s = 0; s < 256; ++s) {
        asm volatile("cp.async.wait_group 4;");
        __syncthreads();

        const __half* bp = dsmh + stage * SSTAGEH;

        // Halo from t-1 (pairs 2,3) and t-2 (pairs 0,1).
        unsigned s1p01 = __shfl_up_sync(0xffffffffu, p01, 1);
        unsigned s1p23 = __shfl_up_sync(0xffffffffu, p23, 1);
        unsigned s1q01 = __shfl_up_sync(0xffffffffu, q01, 1);
        unsigned s1q23 = __shfl_up_sync(0xffffffffu, q23, 1);
        unsigned s2p01 = __shfl_up_sync(0xffffffffu, p01, 2);
        unsigned s2p23 = __shfl_up_sync(0xffffffffu, p23, 2);
        unsigned s2q01 = __shfl_up_sync(0xffffffffu, q01, 2);
        unsigned s2q23 = __shfl_up_sync(0xffffffffu, q23, 2);
        if (lane <= 1) {
            if (w == 0) {
                s2p01 = s2p23 = s2q01 = s2q23 = INF2;
                if (lane == 0) {
                    s1p01 = s1p23 = s1q01 = INF2;
                    s1q23 = (s == 0) ? 0xFC007C00u : INF2;   // seed ca[-1][-1]
                }
            } else {
                uint4 m31 = swm[s & 1][w - 1][1];
                if (lane == 0) {
                    uint4 m30 = swm[s & 1][w - 1][0];
                    s2p01 = m30.x; s2p23 = m30.y; s2q01 = m30.z; s2q23 = m30.w;
                    s1p01 = m31.x; s1p23 = m31.y; s1q01 = m31.z; s1q23 = m31.w;
                } else {   // lane 1: t-2 = warp w-1 lane 31
                    s2p01 = m31.x; s2p23 = m31.y; s2q01 = m31.z; s2q23 = m31.w;
                }
            }
        }

        unsigned a1[6]  = {s2p01, s2p23, s1p01, s1p23, p01, p23};   // prev1 = P
        unsigned Qv[6]  = {s2q01, s2q23, s1q01, s1q23, q01, q23};
        unsigned a1s[6], a2s[6];                                    // P>>1, Q>>1
        a1s[0] = SH(INF2, a1[0]);
        a2s[0] = SH(INF2, Qv[0]);
        #pragma unroll
        for (int k = 1; k < 6; ++k) {
            a1s[k] = SH(a1[k-1], a1[k]);
            a2s[k] = SH(Qv[k-1], Qv[k]);
        }

        unsigned nq01 = INF2, nq23 = INF2;   // level 6 own pairs (new q)
        #pragma unroll
        for (int l = 0; l < 8; ++l) {
            const __half* rp = bp + l * SROWH + j0;
            uint2 c0 = *(const uint2*)(rp);
            uint2 c1 = *(const uint2*)(rp + 4);
            uint2 c2 = *(const uint2*)(rp + 8);
            unsigned C[6] = {c0.x, c0.y, c1.x, c1.y, c2.x, c2.y};

            unsigned cur[6];
            #pragma unroll
            for (int k = 0; k < 6; ++k)
                cur[k] = hmax2u(C[k], hmin2u(hmin2u(a1[k], a1s[k]), a2s[k]));

            unsigned curs0 = SH(INF2, cur[0]);
            a2s[0] = a1s[0]; a1s[0] = curs0; a1[0] = cur[0];
            #pragma unroll
            for (int k = 1; k < 6; ++k) {
                unsigned cs = SH(cur[k-1], cur[k]);
                a2s[k] = a1s[k]; a1s[k] = cs; a1[k] = cur[k];
            }
            if (l == 6) { nq01 = cur[4]; nq23 = cur[5]; }
        }

        p01 = a1[4]; p23 = a1[5]; q01 = nq01; q23 = nq23;

        if (lane >= 30)
            swm[(s + 1) & 1][w][lane - 30] = make_uint4(p01, p23, q01, q23);
        if (s == 255) res = __high2float(*(__half2*)&nq23);   // diag 2046, col 1023

        // Availability trigger: group done_groups first needed at s = 16g-5.
        if (s == s_trig) {
            int tn = (done_groups <= 7) ? done_groups + 1 : 15 - done_groups;
            while (cnt[done_groups] < tn) { }
            __threadfence();
            ++done_groups;
            s_trig = (done_groups < 15) ? 16 * done_groups - 5 : 0x7FFFFFFF;
        }

        // Issue stage s+5 into the buffer consumed at body s-1 (race-free).
        {
            int st2 = stage + (RING - 1); if (st2 >= RING) st2 -= RING;
            int dbase = 8 * (s + RING - 1);
            #pragma unroll
            for (int k = 0; k < 8; ++k)
                if (DP_ON(dbase + k))
                    cpa8(smu + (st2 * 8 + k) * (SROWH * 2),
                         SC + (size_t)(dbase + k) * RS + j0);
            asm volatile("cp.async.commit_group;");
        }
        if (++stage == RING) stage = 0;
    }

    if (t == 255) {
        g_bdist[b] = res;
        __threadfence();
        unsigned tk = atomicAdd(&g_done, 1u);
        if (tk == BB - 1) {                  // last dp CTA: final sqrt-mean
            __threadfence();
            float sum = 0.f;
            #pragma unroll 1
            for (int i = 0; i < BB; ++i)
                sum += sqrtf(((volatile float*)g_bdist)[i]);
            outp[0] = sum * (1.0f / BB);
        }
    }
    #undef DP_ON
}

// ---------------------------------------------------------------------------
// Fused kernel: bids 0..31 = DP consumers (wave-1 resident; never block
// producers => no deadlock), bids 32..2079 = cost producers.
// ---------------------------------------------------------------------------
__global__ void __launch_bounds__(256, 2) fused_kernel(const float* __restrict__ pred,
                                                       const float* __restrict__ targ,
                                                       float* outp) {
    extern __shared__ __align__(16) char dyn[];
    if (blockIdx.x < 32) dp_role(dyn, outp);
    else                 cost_role(dyn, pred, targ, blockIdx.x - 32);
}

// ---------------------------------------------------------------------------
extern "C" void kernel_launch(void* const* d_in, const int* in_sizes, int n_in,
                              void* d_out, int out_size) {
    const float* pred = (const float*)d_in[0];
    const float* targ = (const float*)d_in[1];
    (void)in_sizes; (void)n_in; (void)out_size;

    cudaFuncSetAttribute(fused_kernel,
                         cudaFuncAttributeMaxDynamicSharedMemorySize, DPDYN);

    pre_kernel<<<8448, 256>>>(pred, targ);
    fused_kernel<<<2080, 256, DPDYN>>>(pred, targ, (float*)d_out);
}